// round 2
// baseline (speedup 1.0000x reference)
#include <cuda_runtime.h>
#include <cuda_bf16.h>

// out[n, d] = dist[n] * w[d]   (N = 1,000,000 rows, DIM = 256, fp32)
// Pure HBM-store-bound: 1.024 GB written, ~4 MB read.
// Strategy: one float4 STG.128 per thread, warp-uniform dist load,
// weight vector staged once per block in shared memory.

#define DIM 256
#define VEC4_PER_ROW (DIM / 4)   // 64
#define TPB 256

__global__ __launch_bounds__(TPB) void outer_product_kernel(
    const float* __restrict__ dist,
    const float* __restrict__ weight,
    float4* __restrict__ out,
    int n_rows)
{
    __shared__ float4 sw[VEC4_PER_ROW];
    if (threadIdx.x < VEC4_PER_ROW) {
        sw[threadIdx.x] = reinterpret_cast<const float4*>(weight)[threadIdx.x];
    }
    __syncthreads();

    // Linear index over float4 output elements.
    // i >> 6 = row, i & 63 = float4 column. Within a warp, row is constant
    // (block base is 256-aligned, warp base 32-aligned, 64 vec4 per row),
    // so the dist load is a warp-uniform broadcast (L1-resident).
    long long i = (long long)blockIdx.x * TPB + threadIdx.x;
    long long total = (long long)n_rows * VEC4_PER_ROW;
    if (i >= total) return;

    int row  = (int)(i >> 6);
    int col4 = (int)(i & (VEC4_PER_ROW - 1));

    float d = __ldg(&dist[row]);
    float4 w = sw[col4];

    float4 r;
    r.x = d * w.x;
    r.y = d * w.y;
    r.z = d * w.z;
    r.w = d * w.w;
    out[i] = r;
}

extern "C" void kernel_launch(void* const* d_in, const int* in_sizes, int n_in,
                              void* d_out, int out_size)
{
    const float* dist   = (const float*)d_in[0];
    const float* weight = (const float*)d_in[1];
    float4* out         = (float4*)d_out;

    int n_rows = in_sizes[0];                 // 1,000,000
    long long total_vec4 = (long long)n_rows * VEC4_PER_ROW;   // 64M
    int grid = (int)((total_vec4 + TPB - 1) / TPB);            // 262,144

    outer_product_kernel<<<grid, TPB>>>(dist, weight, out, n_rows);
}

// round 5
// speedup vs baseline: 1.2411x; 1.2411x over previous
#include <cuda_runtime.h>
#include <cuda_bf16.h>

// out[n, d] = dist[n] * w[d]   (N = 1,000,000 rows, DIM = 256, fp32)
// R2: single-wave persistent kernel. 1184 CTAs x 256 thr = one full wave
// (148 SMs x 8 CTAs). Grid-stride is a multiple of 64 vec4/row, so each
// thread owns a fixed column -> weight float4 lives in registers; no smem,
// no barrier, no CTA churn. x4 unroll => 4 independent STG.128 in flight
// per thread to keep the DRAM write queue deep.

#define DIM 256
#define VEC4_PER_ROW (DIM / 4)   // 64
#define TPB 256
#define NBLK 1184                // 148 SMs * 8 resident CTAs -> 1 wave

__global__ __launch_bounds__(TPB) void outer_product_persistent(
    const float* __restrict__ dist,
    const float* __restrict__ weight,
    float4* __restrict__ out,
    int n_rows)
{
    // Fixed column for this thread (stride is a multiple of 64).
    const int col4 = threadIdx.x & (VEC4_PER_ROW - 1);
    const float4 w = __ldg(&reinterpret_cast<const float4*>(weight)[col4]);

    const long long stride = (long long)gridDim.x * TPB;       // multiple of 64
    const long long total  = (long long)n_rows * VEC4_PER_ROW; // 64M vec4
    long long i = (long long)blockIdx.x * TPB + threadIdx.x;

    // Main loop: 4 independent rows per iteration.
    for (; i + 3 * stride < total; i += 4 * stride) {
        // Front-batch the dist loads (warp-uniform broadcasts).
        const float d0 = __ldg(&dist[(int)( i               >> 6)]);
        const float d1 = __ldg(&dist[(int)((i +     stride) >> 6)]);
        const float d2 = __ldg(&dist[(int)((i + 2 * stride) >> 6)]);
        const float d3 = __ldg(&dist[(int)((i + 3 * stride) >> 6)]);

        float4 r0, r1, r2, r3;
        r0.x = d0 * w.x; r0.y = d0 * w.y; r0.z = d0 * w.z; r0.w = d0 * w.w;
        r1.x = d1 * w.x; r1.y = d1 * w.y; r1.z = d1 * w.z; r1.w = d1 * w.w;
        r2.x = d2 * w.x; r2.y = d2 * w.y; r2.z = d2 * w.z; r2.w = d2 * w.w;
        r3.x = d3 * w.x; r3.y = d3 * w.y; r3.z = d3 * w.z; r3.w = d3 * w.w;

        out[i]              = r0;
        out[i +     stride] = r1;
        out[i + 2 * stride] = r2;
        out[i + 3 * stride] = r3;
    }

    // Tail.
    for (; i < total; i += stride) {
        const float d = __ldg(&dist[(int)(i >> 6)]);
        float4 r;
        r.x = d * w.x; r.y = d * w.y; r.z = d * w.z; r.w = d * w.w;
        out[i] = r;
    }
}

extern "C" void kernel_launch(void* const* d_in, const int* in_sizes, int n_in,
                              void* d_out, int out_size)
{
    const float* dist   = (const float*)d_in[0];
    const float* weight = (const float*)d_in[1];
    float4* out         = (float4*)d_out;

    int n_rows = in_sizes[0];   // 1,000,000

    outer_product_persistent<<<NBLK, TPB>>>(dist, weight, out, n_rows);
}

// round 7
// speedup vs baseline: 1.3960x; 1.1248x over previous
#include <cuda_runtime.h>
#include <cuda_bf16.h>

// out[n, d] = dist[n] * w[d]   (N = 1,000,000 rows, DIM = 256, fp32)
// R5: single-wave persistent kernel, x8 unroll, streaming (evict-first)
// stores via __stcs to keep the L2->DRAM writeback stream dense.
// Each thread owns a fixed column (stride is a multiple of 64 vec4/row),
// so the weight float4 stays in registers; dist loads are warp-uniform.

#define DIM 256
#define VEC4_PER_ROW (DIM / 4)   // 64
#define TPB 256
#define NBLK 1184                // 148 SMs * 8 resident CTAs -> 1 wave
#define UNROLL 8

__global__ __launch_bounds__(TPB) void outer_product_persistent(
    const float* __restrict__ dist,
    const float* __restrict__ weight,
    float4* __restrict__ out,
    int n_rows)
{
    const int col4 = threadIdx.x & (VEC4_PER_ROW - 1);
    const float4 w = __ldg(&reinterpret_cast<const float4*>(weight)[col4]);

    const long long stride = (long long)gridDim.x * TPB;        // multiple of 64
    const long long total  = (long long)n_rows * VEC4_PER_ROW;  // 64M vec4
    long long i = (long long)blockIdx.x * TPB + threadIdx.x;

    // Main loop: 8 rows per iteration. Front-batch the (warp-uniform) dist
    // loads, then compute+store each element immediately so register live
    // ranges stay short (occupancy stays at 8 CTAs/SM).
    for (; i + (UNROLL - 1) * stride < total; i += (long long)UNROLL * stride) {
        float d[UNROLL];
#pragma unroll
        for (int j = 0; j < UNROLL; j++) {
            d[j] = __ldg(&dist[(int)((i + j * stride) >> 6)]);
        }
#pragma unroll
        for (int j = 0; j < UNROLL; j++) {
            float4 r;
            r.x = d[j] * w.x;
            r.y = d[j] * w.y;
            r.z = d[j] * w.z;
            r.w = d[j] * w.w;
            __stcs(&out[i + j * stride], r);   // evict-first streaming store
        }
    }

    // Tail.
    for (; i < total; i += stride) {
        const float dd = __ldg(&dist[(int)(i >> 6)]);
        float4 r;
        r.x = dd * w.x; r.y = dd * w.y; r.z = dd * w.z; r.w = dd * w.w;
        __stcs(&out[i], r);
    }
}

extern "C" void kernel_launch(void* const* d_in, const int* in_sizes, int n_in,
                              void* d_out, int out_size)
{
    const float* dist   = (const float*)d_in[0];
    const float* weight = (const float*)d_in[1];
    float4* out         = (float4*)d_out;

    int n_rows = in_sizes[0];   // 1,000,000

    outer_product_persistent<<<NBLK, TPB>>>(dist, weight, out, n_rows);
}